// round 4
// baseline (speedup 1.0000x reference)
#include <cuda_runtime.h>
#include <cstdint>

// ---------------------------------------------------------------------------
// UniformSpline log-prob (inverse rational-quadratic spline logdet)
//   x:  (2097152, 8) f32     uw,uh: (8,128) f32    ud: (8,127) f32
//   out: (2097152, 8) f32 = log(0.5) - logabsdet(x) (identity tails -> log 0.5)
//
// 3 kernels: build tables (tiny) -> build direct-index LUT (tiny) -> main pass.
// ---------------------------------------------------------------------------

#define NCH   8
#define NBINS 128

// Per-channel tables (scratch; __device__ globals are the allowed scratch path)
__device__ float  g_edges[NCH * (NBINS + 1)];          // cumheights, exact endpoints -1, 1
__device__ float4 g_pack [NCH * (NBINS + 1)];          // per bin: {h, delta, d_k, d_{k+1}}
__device__ unsigned char g_lut[NCH * 1024];            // quantized y -> bin index (candidate)

// ---------------------------------------------------------------------------
// Kernel A: softmax + cumsum per channel -> knot edges; pack per-bin params.
// 16 warps: warp w<8 -> widths of channel w, warp w>=8 -> heights of channel w-8.
// ---------------------------------------------------------------------------
__global__ void build_tables_kernel(const float* __restrict__ uw,
                                    const float* __restrict__ uh,
                                    const float* __restrict__ ud)
{
    __shared__ float sE[2][NCH][NBINS + 1];   // [0]=cumwidths, [1]=cumheights

    const int tid  = threadIdx.x;
    const int w    = tid >> 5;
    const int l    = tid & 31;
    const int part = w >> 3;           // 0: widths, 1: heights
    const int c    = w & 7;
    const float* src = part ? uh : uw;

    // each lane handles 4 consecutive bins
    float u[4];
#pragma unroll
    for (int k = 0; k < 4; k++) u[k] = 10.0f * src[c * NBINS + l * 4 + k];

    float m = fmaxf(fmaxf(u[0], u[1]), fmaxf(u[2], u[3]));
#pragma unroll
    for (int off = 16; off; off >>= 1) m = fmaxf(m, __shfl_xor_sync(0xffffffffu, m, off));

    float e[4];
#pragma unroll
    for (int k = 0; k < 4; k++) e[k] = expf(u[k] - m);
    float ls = e[0] + e[1] + e[2] + e[3];

    // inclusive warp scan of lane sums
    float sc = ls;
#pragma unroll
    for (int off = 1; off < 32; off <<= 1) {
        float v = __shfl_up_sync(0xffffffffu, sc, off);
        if (l >= off) sc += v;
    }
    const float S    = __shfl_sync(0xffffffffu, sc, 31);
    const float invS = 1.0f / S;
    float ce = sc - ls;                 // exclusive prefix of exp-sums

    // sizes_j = 1e-3 + (1 - 1e-3*128) * softmax_j ; cum -> edge[j+1] = 2*cum - 1
#pragma unroll
    for (int k = 0; k < 4; k++) {
        ce += e[k];
        int j = l * 4 + k;
        float cum = 1e-3f * (float)(j + 1) + 0.872f * ce * invS;
        float val = 2.0f * cum - 1.0f;
        sE[part][c][j + 1] = (j == NBINS - 1) ? 1.0f : val;   // clamp right end
    }
    if (l == 0) sE[part][c][0] = -1.0f;                        // clamp left end
    __syncthreads();

    // tail derivative constant: MIN_DERIVATIVE + softplus(DEFAULT_INIT) == 1.0
    const float DI = logf(expf(1.0f - 1e-3f) - 1.0f);
    const float DT = 1e-3f + log1pf(expf(DI));

    // pack per-bin params {h, delta, d_k, d_{k+1}}
    for (int e2 = tid; e2 < NCH * NBINS; e2 += blockDim.x) {
        int cc = e2 >> 7, k = e2 & 127;
        float h  = sE[1][cc][k + 1] - sE[1][cc][k];
        float wd = sE[0][cc][k + 1] - sE[0][cc][k];
        float dl = h / wd;
        float d0 = (k == 0)         ? DT : 1e-3f + log1pf(expf(ud[cc * (NBINS - 1) + k - 1]));
        float d1 = (k == NBINS - 1) ? DT : 1e-3f + log1pf(expf(ud[cc * (NBINS - 1) + k]));
        g_pack[cc * (NBINS + 1) + k] = make_float4(h, dl, d0, d1);
    }
    // export cumheight edges (search domain)
    for (int e2 = tid; e2 < NCH * (NBINS + 1); e2 += blockDim.x) {
        int cc = e2 / (NBINS + 1), k = e2 - cc * (NBINS + 1);
        g_edges[e2] = sE[1][cc][k];
    }
}

// ---------------------------------------------------------------------------
// Kernel A2: direct-index LUT. Cell width 2/1024 < min bin height 2e-3, so the
// true bin index is LUT[q] or LUT[q]+1 (resolved with ONE compare in kernel B).
// ---------------------------------------------------------------------------
__global__ void build_lut_kernel()
{
    int t = blockIdx.x * blockDim.x + threadIdx.x;   // 8192 threads
    int c = t >> 10, q = t & 1023;
    float v = (float)q * (1.0f / 512.0f) - 1.0f;
    const float* E = g_edges + c * (NBINS + 1);
    int lo = 0, hi = NBINS - 1;
    while (lo < hi) {                                 // largest k in [0,127] with E[k] <= v
        int mid = (lo + hi + 1) >> 1;
        if (E[mid] <= v) lo = mid; else hi = mid - 1;
    }
    g_lut[t] = (unsigned char)lo;
}

// ---------------------------------------------------------------------------
// Kernel B: main pass. float4 I/O: thread's 4 elements are 4 consecutive
// channels of one position. Tables staged in smem.
// ---------------------------------------------------------------------------
#define ESTRIDE 132   // padded edge stride: 132 % 32 == 4 -> channels hit distinct banks

__global__ void __launch_bounds__(256)
spline_main_kernel(const float4* __restrict__ x4, float4* __restrict__ o4, int n4)
{
    __shared__ float         sE[NCH * ESTRIDE];
    __shared__ float4        sP[NCH * (NBINS + 1)];
    __shared__ unsigned char sL[NCH * 1024];

    const int tid = threadIdx.x;
    for (int i = tid; i < NCH * (NBINS + 1); i += 256) {
        int c = i / (NBINS + 1), k = i - c * (NBINS + 1);
        sE[c * ESTRIDE + k] = g_edges[i];
    }
    for (int i = tid; i < NCH * (NBINS + 1); i += 256) sP[i] = g_pack[i];
    {
        const int4* gl = (const int4*)g_lut;
        int4* sl = (int4*)sL;
        for (int i = tid; i < (NCH * 1024) / 16; i += 256) sl[i] = gl[i];
    }
    __syncthreads();

    const float LOG_HALF = -0.6931471805599453f;
    const int stride = gridDim.x * blockDim.x;

    for (int i = blockIdx.x * blockDim.x + tid; i < n4; i += stride) {
        float4 xv = x4[i];
        const int cb = (i & 1) << 2;                  // channel base: 0 or 4
        float xs[4] = {xv.x, xv.y, xv.z, xv.w};
        float r[4];
#pragma unroll
        for (int j = 0; j < 4; j++) {
            const int c = cb + j;
            const float x  = xs[j];
            const float xc = fminf(fmaxf(x, -1.0f), 1.0f);

            // direct-index LUT + single compare -> bin index
            int q = (int)((xc + 1.0f) * 512.0f);
            q = (q > 1023) ? 1023 : q;
            int idx = (int)sL[(c << 10) + q];
            float e0 = sE[c * ESTRIDE + idx];
            float e1 = sE[c * ESTRIDE + idx + 1];
            bool inc = (idx < NBINS - 1) && (xc >= e1);
            float ich = inc ? e1 : e0;
            idx += inc;

            float4 p = sP[c * (NBINS + 1) + idx];     // {h, delta, d0, d1}

            // quadratic inverse solve (Durkan et al.)
            float dy   = xc - ich;
            float t    = p.z + p.w - 2.0f * p.y;
            float aa   = dy * t + p.x * (p.y - p.z);
            float bb   = p.x * p.z - dy * t;
            float cc2  = -p.y * dy;
            float disc = fmaxf(bb * bb - 4.0f * aa * cc2, 0.0f);
            float root = __fdividef(2.0f * cc2, -bb - sqrtf(disc));
            float th   = root * (1.0f - root);
            float den  = p.y + t * th;
            float omr  = 1.0f - root;
            float dnum = p.y * p.y * (p.w * root * root + 2.0f * p.y * th + p.z * omr * omr);
            float lad  = __logf(__fdividef(dnum, den * den));

            bool inside = (x >= -1.0f) && (x <= 1.0f);
            r[j] = inside ? (LOG_HALF - lad) : LOG_HALF;
        }
        o4[i] = make_float4(r[0], r[1], r[2], r[3]);
    }
}

// ---------------------------------------------------------------------------
extern "C" void kernel_launch(void* const* d_in, const int* in_sizes, int n_in,
                              void* d_out, int out_size)
{
    const float* x  = (const float*)d_in[0];
    const float* uw = (const float*)d_in[1];
    const float* uh = (const float*)d_in[2];
    const float* ud = (const float*)d_in[3];

    build_tables_kernel<<<1, 512>>>(uw, uh, ud);
    build_lut_kernel<<<32, 256>>>();

    const int n4 = out_size / 4;
    spline_main_kernel<<<592, 256>>>((const float4*)x, (float4*)d_out, n4);
}

// round 5
// speedup vs baseline: 1.0518x; 1.0518x over previous
#include <cuda_runtime.h>
#include <cstdint>

// ---------------------------------------------------------------------------
// UniformSpline log-prob (inverse rational-quadratic spline logdet)
//   x: (2097152, 8) f32   uw,uh: (8,128) f32   ud: (8,127) f32
//   out = log(0.5) - logabsdet(x), identity tails -> log(0.5)
//
// Single fused kernel: every block builds the tiny per-channel tables + a
// direct-index LUT in shared memory (cheap, fully parallel across blocks),
// then runs a grid-strided float4 main loop.
// ---------------------------------------------------------------------------

#define NCH     8
#define NBINS   128
#define ESTRIDE 132          // padded edge row stride
#define NLUT    1024         // LUT cells per channel; cell width 2/1024 < min bin height 2e-3

__device__ __forceinline__ float softplus_md(float v) {
    // MIN_DERIVATIVE + softplus(v)
    return 1e-3f + log1pf(expf(v));
}

// Per-warp (one channel) edge computation: softmax(10*u) with min bin size,
// cumsum -> knots in [-1, 1]. Lane l owns bins 4l..4l+3; fills e[0..4] =
// edges at indices 4l .. 4l+4 (e[0] is the left edge of bin 4l).
__device__ __forceinline__ void edges4(const float* __restrict__ src_row,
                                       int l, float e[5]) {
    float u[4], ex[4];
#pragma unroll
    for (int k = 0; k < 4; k++) u[k] = 10.0f * src_row[l * 4 + k];
    float m = fmaxf(fmaxf(u[0], u[1]), fmaxf(u[2], u[3]));
#pragma unroll
    for (int off = 16; off; off >>= 1) m = fmaxf(m, __shfl_xor_sync(0xffffffffu, m, off));
#pragma unroll
    for (int k = 0; k < 4; k++) ex[k] = expf(u[k] - m);
    float ls = ex[0] + ex[1] + ex[2] + ex[3];

    float sc = ls;                               // inclusive scan of lane sums
#pragma unroll
    for (int off = 1; off < 32; off <<= 1) {
        float v = __shfl_up_sync(0xffffffffu, sc, off);
        if (l >= off) sc += v;
    }
    const float invS = 1.0f / __shfl_sync(0xffffffffu, sc, 31);
    float ce = sc - ls;                          // exclusive prefix

    // edge[j] = 2*(1e-3*j + (1 - 0.128)*cumsm) - 1, ends clamped to +-1
    e[0] = (l == 0) ? -1.0f
                    : 2.0f * (1e-3f * (float)(4 * l) + 0.872f * ce * invS) - 1.0f;
#pragma unroll
    for (int k = 0; k < 4; k++) {
        ce += ex[k];
        int j = l * 4 + k + 1;
        e[k + 1] = (j == NBINS) ? 1.0f
                                : 2.0f * (1e-3f * (float)j + 0.872f * ce * invS) - 1.0f;
    }
}

__global__ void __launch_bounds__(256)
spline_fused_kernel(const float4* __restrict__ x4, float4* __restrict__ o4, int n4,
                    const float* __restrict__ uw, const float* __restrict__ uh,
                    const float* __restrict__ ud)
{
    __shared__ float         sE[NCH * ESTRIDE];          // cumheight edges (129 used/row)
    __shared__ float4        sP[NCH * (NBINS + 1)];      // per bin {h, delta, d_k, d_{k+1}} + sentinel
    __shared__ unsigned char sL[NCH * NLUT];             // quantized y -> candidate bin

    const int tid = threadIdx.x;
    const int c0  = tid >> 5;        // warp id == channel (256 threads = 8 warps)
    const int l   = tid & 31;

    // ---- table build: warp c0 handles channel c0, all in registers ----
    {
        // tail derivative constant: softplus(DEFAULT_INIT)+1e-3 == 1.0
        const float DI = logf(expf(1.0f - 1e-3f) - 1.0f);
        const float DT = softplus_md(DI);

        float ew[5], eh[5];
        edges4(uw + c0 * NBINS, l, ew);
        edges4(uh + c0 * NBINS, l, eh);

        // derivatives at knots 4l .. 4l+4
        float dd[5];
#pragma unroll
        for (int m2 = 0; m2 < 5; m2++) {
            int k = 4 * l + m2;
            dd[m2] = (k == 0 || k == NBINS) ? DT
                     : softplus_md(ud[c0 * (NBINS - 1) + k - 1]);
        }

        float* Er = sE + c0 * ESTRIDE;
#pragma unroll
        for (int k = 0; k < 4; k++) Er[4 * l + k] = eh[k];
        if (l == 31) Er[NBINS] = eh[4];

        float4* Pr = sP + c0 * (NBINS + 1);
#pragma unroll
        for (int k = 0; k < 4; k++) {
            float h  = eh[k + 1] - eh[k];
            float wd = ew[k + 1] - ew[k];
            Pr[4 * l + k] = make_float4(h, h / wd, dd[k], dd[k + 1]);
        }
        if (l == 31) {  // sentinel bin 128: dy==0 path, d0 = derivatives[128] = DT
            float h = eh[4] - eh[3];
            Pr[NBINS] = make_float4(h, h / (ew[4] - ew[3]), DT, DT);
        }
    }
    __syncthreads();

    // ---- LUT build: thread -> 32 consecutive cells of channel tid>>5 ----
    {
        const float* E = sE + c0 * ESTRIDE;
        const int cell0 = l * 32;
        float v = (float)cell0 * (1.0f / 512.0f) - 1.0f;
        int lo = 0;                                  // largest k<=127 with E[k] <= v
#pragma unroll
        for (int step = 64; step; step >>= 1)
            if (lo + step <= NBINS - 1 && E[lo + step] <= v) lo += step;
        unsigned char* L = sL + c0 * NLUT + cell0;
        for (int q = 0; q < 32; q++) {
            float vq = (float)(cell0 + q) * (1.0f / 512.0f) - 1.0f;
            while (lo < NBINS - 1 && E[lo + 1] <= vq) lo++;
            L[q] = (unsigned char)lo;
        }
    }
    __syncthreads();

    // ---- main pass: each thread's float4 = 4 consecutive channels ----
    const float LOG_HALF = -0.6931471805599453f;
    const int stride = gridDim.x * blockDim.x;

    for (int i = blockIdx.x * blockDim.x + tid; i < n4; i += stride) {
        float4 xv = x4[i];
        const int cb = (i & 1) << 2;                 // channel base: 0 or 4
        float xs[4] = {xv.x, xv.y, xv.z, xv.w};
        float r[4];
#pragma unroll
        for (int j = 0; j < 4; j++) {
            const int c = cb + j;
            const float x  = xs[j];
            const float xc = fminf(fmaxf(x, -1.0f), 1.0f);

            int q = (int)((xc + 1.0f) * 512.0f);
            q = min(q, NLUT - 1);
            int idx = (int)sL[(c << 10) + q];

            float e0 = sE[c * ESTRIDE + idx];
            float4 p = sP[c * (NBINS + 1) + idx];    // {h, delta, d0, d1}
            float dy = xc - e0;
            if (dy >= p.x) {                          // at most one edge per LUT cell
                dy -= p.x;
                p = sP[c * (NBINS + 1) + idx + 1];
            }

            // stable quadratic inverse (citardauq form)
            float t    = p.z + p.w - 2.0f * p.y;
            float dyt  = dy * t;
            float aa   = fmaf(p.x, p.y - p.z, dyt);
            float bb   = fmaf(p.x, p.z, -dyt);
            float cc   = -p.y * dy;
            float disc = fmaxf(fmaf(bb, bb, -4.0f * aa * cc), 0.0f);
            float s;  asm("sqrt.approx.f32 %0, %1;" : "=f"(s) : "f"(disc));
            float root = __fdividef(cc + cc, -bb - s);
            float th   = root - root * root;
            float den  = fmaf(t, th, p.y);
            float omr  = 1.0f - root;
            float pp   = fmaf(p.w, root * root,
                         fmaf(p.z, omr * omr, (p.y + p.y) * th));
            float dnum = (p.y * p.y) * pp;
            float lad  = __logf(__fdividef(dnum, den * den));

            bool inside = fabsf(x) <= 1.0f;
            r[j] = inside ? (LOG_HALF - lad) : LOG_HALF;
        }
        o4[i] = make_float4(r[0], r[1], r[2], r[3]);
    }
}

// ---------------------------------------------------------------------------
extern "C" void kernel_launch(void* const* d_in, const int* in_sizes, int n_in,
                              void* d_out, int out_size)
{
    const float* x  = (const float*)d_in[0];
    const float* uw = (const float*)d_in[1];
    const float* uh = (const float*)d_in[2];
    const float* ud = (const float*)d_in[3];

    const int n4 = out_size / 4;
    spline_fused_kernel<<<592, 256>>>((const float4*)x, (float4*)d_out, n4,
                                      uw, uh, ud);
}

// round 6
// speedup vs baseline: 1.1041x; 1.0497x over previous
#include <cuda_runtime.h>
#include <cstdint>

// ---------------------------------------------------------------------------
// UniformSpline log-prob (inverse rational-quadratic spline logdet)
//   x: (2097152, 8) f32   uw,uh: (8,128) f32   ud: (8,127) f32
//   out = log(0.5) - logabsdet(x), identity tails -> log(0.5)
//
// Single fused kernel; each thread iteration processes ONE position (all 8
// channels) so the channel index is a compile-time constant in the unrolled
// body -> shared-memory offsets fold to immediates.
// ---------------------------------------------------------------------------

#define NCH   8
#define NBINS 128
#define NLUT  1024     // cell width 2/1024 < min bin height 2e-3 -> <=1 edge per cell

__device__ __forceinline__ float softplus_md(float v) {
    return 1e-3f + log1pf(expf(v));      // MIN_DERIVATIVE + softplus
}

// Per-warp (one channel) softmax(10u)+min-size cumsum -> knots in [-1,1].
// Lane l owns bins 4l..4l+3; e[0..4] = edges 4l..4l+4.
__device__ __forceinline__ void edges4(const float* __restrict__ src_row,
                                       int l, float e[5]) {
    float u[4], ex[4];
#pragma unroll
    for (int k = 0; k < 4; k++) u[k] = 10.0f * src_row[l * 4 + k];
    float m = fmaxf(fmaxf(u[0], u[1]), fmaxf(u[2], u[3]));
#pragma unroll
    for (int off = 16; off; off >>= 1) m = fmaxf(m, __shfl_xor_sync(0xffffffffu, m, off));
#pragma unroll
    for (int k = 0; k < 4; k++) ex[k] = expf(u[k] - m);
    float ls = ex[0] + ex[1] + ex[2] + ex[3];

    float sc = ls;
#pragma unroll
    for (int off = 1; off < 32; off <<= 1) {
        float v = __shfl_up_sync(0xffffffffu, sc, off);
        if (l >= off) sc += v;
    }
    const float invS = 1.0f / __shfl_sync(0xffffffffu, sc, 31);
    float ce = sc - ls;

    e[0] = (l == 0) ? -1.0f
                    : 2.0f * (1e-3f * (float)(4 * l) + 0.872f * ce * invS) - 1.0f;
#pragma unroll
    for (int k = 0; k < 4; k++) {
        ce += ex[k];
        int j = l * 4 + k + 1;
        e[k + 1] = (j == NBINS) ? 1.0f
                                : 2.0f * (1e-3f * (float)j + 0.872f * ce * invS) - 1.0f;
    }
}

__global__ void __launch_bounds__(256, 4)
spline_fused_kernel(const float4* __restrict__ x4, float4* __restrict__ o4, int npairs,
                    const float* __restrict__ uw, const float* __restrict__ uh,
                    const float* __restrict__ ud)
{
    __shared__ float         sE[NCH][NBINS + 1];     // left knot (cumheights)
    __shared__ float4        sP[NCH][NBINS + 1];     // {h, delta, d0, t=d0+d1-2delta} + sentinel
    __shared__ unsigned char sL[NCH][NLUT];          // y -> candidate bin

    const int tid = threadIdx.x;
    const int c0  = tid >> 5;            // warp == channel (8 warps)
    const int l   = tid & 31;

    // ---- per-channel table build (registers + shuffles) ----
    {
        const float DI = logf(expf(1.0f - 1e-3f) - 1.0f);
        const float DT = softplus_md(DI);           // tail derivative == 1.0

        float ew[5], eh[5];
        edges4(uw + c0 * NBINS, l, ew);
        edges4(uh + c0 * NBINS, l, eh);

        float dd[5];
#pragma unroll
        for (int m2 = 0; m2 < 5; m2++) {
            int k = 4 * l + m2;
            dd[m2] = (k == 0 || k == NBINS) ? DT
                     : softplus_md(ud[c0 * (NBINS - 1) + k - 1]);
        }

#pragma unroll
        for (int k = 0; k < 4; k++) sE[c0][4 * l + k] = eh[k];
        if (l == 31) sE[c0][NBINS] = eh[4];

#pragma unroll
        for (int k = 0; k < 4; k++) {
            float h  = eh[k + 1] - eh[k];
            float dl = h / (ew[k + 1] - ew[k]);
            sP[c0][4 * l + k] = make_float4(h, dl, dd[k], dd[k] + dd[k + 1] - 2.0f * dl);
        }
        if (l == 31) {                   // sentinel bin 128 (hit only with dy==0)
            float h  = eh[4] - eh[3];
            float dl = h / (ew[4] - ew[3]);
            sP[c0][NBINS] = make_float4(h, dl, DT, 2.0f * (DT - dl));
        }
    }
    __syncthreads();

    // ---- LUT: lane l fills 32 consecutive cells of channel c0 ----
    {
        const float* E = &sE[c0][0];
        const int cell0 = l * 32;
        float v = (float)cell0 * (1.0f / 512.0f) - 1.0f;
        int lo = 0;
#pragma unroll
        for (int step = 64; step; step >>= 1)
            if (lo + step <= NBINS - 1 && E[lo + step] <= v) lo += step;
        unsigned char* L = &sL[c0][cell0];
        for (int q = 0; q < 32; q++) {
            float vq = (float)(cell0 + q) * (1.0f / 512.0f) - 1.0f;
            while (lo < NBINS - 1 && E[lo + 1] <= vq) lo++;
            L[q] = (unsigned char)lo;
        }
    }
    __syncthreads();

    // ---- main pass: one position (8 channels) per iteration ----
    const float LOG_HALF = -0.6931471805599453f;
    const int stride = gridDim.x * blockDim.x;

    for (int p = blockIdx.x * blockDim.x + tid; p < npairs; p += stride) {
        float4 a = x4[2 * p];
        float4 b = x4[2 * p + 1];
        float xs[8] = {a.x, a.y, a.z, a.w, b.x, b.y, b.z, b.w};
        float r[8];
#pragma unroll
        for (int j = 0; j < 8; j++) {                // j == channel, compile-time
            const float x  = xs[j];
            const float xc = fminf(fmaxf(x, -1.0f), 1.0f);

            int q = (int)fmaf(xc, 512.0f, 512.0f);
            q = min(q, NLUT - 1);
            int idx = (int)sL[j][q];

            float  e0 = sE[j][idx];
            float4 pk = sP[j][idx];                  // {h, delta, d0, t}
            float  dy = xc - e0;
            if (dy >= pk.x) {                        // at most one edge per cell
                dy -= pk.x;
                pk = sP[j][idx + 1];
            }

            // stable quadratic inverse (citardauq), t-packed form
            float dmd  = pk.y - pk.z;                // delta - d0
            float dyt  = dy * pk.w;                  // dy * t
            float aa   = fmaf(pk.x, dmd, dyt);
            float bb   = fmaf(pk.x, pk.z, -dyt);
            float g    = pk.y * dy;                  // delta*dy = -c
            float disc = fmaxf(fmaf(bb, bb, 4.0f * aa * g), 0.0f);
            float s;  asm("sqrt.approx.f32 %0, %1;" : "=f"(s) : "f"(disc));
            float root = __fdividef(g + g, bb + s);
            float th   = fmaf(-root, root, root);    // root*(1-root)
            float den  = fmaf(pk.w, th, pk.y);
            float pp   = fmaf(fmaf(pk.w, root, dmd + dmd), root, pk.z);
            float num  = (pk.y * pk.y) * pp;
            float lad  = __logf(__fdividef(num, den * den));

            r[j] = (fabsf(x) <= 1.0f) ? (LOG_HALF - lad) : LOG_HALF;
        }
        o4[2 * p]     = make_float4(r[0], r[1], r[2], r[3]);
        o4[2 * p + 1] = make_float4(r[4], r[5], r[6], r[7]);
    }
}

// ---------------------------------------------------------------------------
extern "C" void kernel_launch(void* const* d_in, const int* in_sizes, int n_in,
                              void* d_out, int out_size)
{
    const float* x  = (const float*)d_in[0];
    const float* uw = (const float*)d_in[1];
    const float* uh = (const float*)d_in[2];
    const float* ud = (const float*)d_in[3];

    const int npairs = out_size / 8;     // one pair of float4 = one position
    spline_fused_kernel<<<592, 256>>>((const float4*)x, (float4*)d_out, npairs,
                                      uw, uh, ud);
}

// round 7
// speedup vs baseline: 1.1261x; 1.0199x over previous
#include <cuda_runtime.h>
#include <cstdint>

// ---------------------------------------------------------------------------
// UniformSpline log-prob (inverse rational-quadratic spline logdet)
//   x: (2097152, 8) f32   uw,uh: (8,128) f32   ud: (8,127) f32
//   out = log(0.5) - logabsdet(x), identity tails -> log(0.5)
//
// Single fused kernel. Fat-cell LUT: each 1/512-wide cell stores the NEXT
// knot value and base bin index, so bin resolution + localization needs only
// one LDS.64 (cell) + one LDS.128 (bin params) per element.
// ---------------------------------------------------------------------------

#define NCH   8
#define NBINS 128
#define NLUT  1024     // cell width 2/1024 < min bin height 2e-3 -> <=1 knot per cell

// dynamic smem layout (bytes)
#define SP_OFF   0                                    // float4 sP[8][129]
#define SP_BYTES (NCH * (NBINS + 1) * 16)
#define SL_OFF   (SP_OFF + SP_BYTES)                  // float2 sL[8][1024]
#define SL_BYTES (NCH * NLUT * 8)
#define SE_OFF   (SL_OFF + SL_BYTES)                  // float sE[8][129]
#define SE_BYTES (NCH * (NBINS + 1) * 4)
#define SMEM_TOTAL (SE_OFF + SE_BYTES)

__device__ __forceinline__ float softplus_md(float v) {
    return 1e-3f + log1pf(expf(v));      // MIN_DERIVATIVE + softplus
}

// Per-warp (one channel) softmax(10u)+min-size cumsum -> knots in [-1,1].
// Lane l owns bins 4l..4l+3; e[0..4] = edges 4l..4l+4.
__device__ __forceinline__ void edges4(const float* __restrict__ src_row,
                                       int l, float e[5]) {
    float u[4], ex[4];
#pragma unroll
    for (int k = 0; k < 4; k++) u[k] = 10.0f * src_row[l * 4 + k];
    float m = fmaxf(fmaxf(u[0], u[1]), fmaxf(u[2], u[3]));
#pragma unroll
    for (int off = 16; off; off >>= 1) m = fmaxf(m, __shfl_xor_sync(0xffffffffu, m, off));
#pragma unroll
    for (int k = 0; k < 4; k++) ex[k] = expf(u[k] - m);
    float ls = ex[0] + ex[1] + ex[2] + ex[3];

    float sc = ls;
#pragma unroll
    for (int off = 1; off < 32; off <<= 1) {
        float v = __shfl_up_sync(0xffffffffu, sc, off);
        if (l >= off) sc += v;
    }
    const float invS = 1.0f / __shfl_sync(0xffffffffu, sc, 31);
    float ce = sc - ls;

    e[0] = (l == 0) ? -1.0f
                    : 2.0f * (1e-3f * (float)(4 * l) + 0.872f * ce * invS) - 1.0f;
#pragma unroll
    for (int k = 0; k < 4; k++) {
        ce += ex[k];
        int j = l * 4 + k + 1;
        e[k + 1] = (j == NBINS) ? 1.0f
                                : 2.0f * (1e-3f * (float)j + 0.872f * ce * invS) - 1.0f;
    }
}

__global__ void __launch_bounds__(512, 2)
spline_fused_kernel(const float4* __restrict__ x4, float4* __restrict__ o4, int npairs,
                    const float* __restrict__ uw, const float* __restrict__ uh,
                    const float* __restrict__ ud)
{
    extern __shared__ unsigned char smem_raw[];
    float4 (*sP)[NBINS + 1] = (float4 (*)[NBINS + 1])(smem_raw + SP_OFF); // {h, delta, d0, t}
    float2 (*sL)[NLUT]      = (float2 (*)[NLUT])     (smem_raw + SL_OFF); // {edge[idx+1], idx}
    float  (*sE)[NBINS + 1] = (float  (*)[NBINS + 1])(smem_raw + SE_OFF); // cumheight knots

    const int tid = threadIdx.x;
    const int l   = tid & 31;

    // ---- per-channel table build: warps 0..7 -> channel = warp id ----
    if (tid < 256) {
        const int c0 = tid >> 5;
        const float DI = logf(expf(1.0f - 1e-3f) - 1.0f);
        const float DT = softplus_md(DI);            // tail derivative == 1.0

        float ew[5], eh[5];
        edges4(uw + c0 * NBINS, l, ew);
        edges4(uh + c0 * NBINS, l, eh);

        float dd[5];
#pragma unroll
        for (int m2 = 0; m2 < 5; m2++) {
            int k = 4 * l + m2;
            dd[m2] = (k == 0 || k == NBINS) ? DT
                     : softplus_md(ud[c0 * (NBINS - 1) + k - 1]);
        }

#pragma unroll
        for (int k = 0; k < 4; k++) sE[c0][4 * l + k] = eh[k];
        if (l == 31) sE[c0][NBINS] = eh[4];

#pragma unroll
        for (int k = 0; k < 4; k++) {
            float h  = eh[k + 1] - eh[k];
            float dl = h / (ew[k + 1] - ew[k]);
            sP[c0][4 * l + k] = make_float4(h, dl, dd[k], dd[k] + dd[k + 1] - 2.0f * dl);
        }
        if (l == 31) {                    // sentinel bin 128 (hit only with dy==0)
            float h  = eh[4] - eh[3];
            float dl = h / (ew[4] - ew[3]);
            sP[c0][NBINS] = make_float4(h, dl, DT, 2.0f * (DT - dl));
        }
    }
    __syncthreads();

    // ---- fat LUT: 64 threads per channel, 16 cells each ----
    {
        const int c     = tid >> 6;
        const int cell0 = (tid & 63) * 16;
        const float* E  = &sE[c][0];
        float v = (float)cell0 * (1.0f / 512.0f) - 1.0f;
        int lo = 0;                                   // largest k<=127 with E[k] <= cell_lo
#pragma unroll
        for (int step = 64; step; step >>= 1)
            if (lo + step <= NBINS - 1 && E[lo + step] <= v) lo += step;
        for (int q = 0; q < 16; q++) {
            float vq = (float)(cell0 + q) * (1.0f / 512.0f) - 1.0f;
            while (lo < NBINS - 1 && E[lo + 1] <= vq) lo++;
            sL[c][cell0 + q] = make_float2(E[lo + 1], __int_as_float(lo));
        }
    }
    __syncthreads();

    // ---- main pass: one position (8 channels) per iteration ----
    const float LOG_HALF = -0.6931471805599453f;
    const int stride = gridDim.x * blockDim.x;

    for (int p = blockIdx.x * blockDim.x + tid; p < npairs; p += stride) {
        float4 a = x4[2 * p];
        float4 b = x4[2 * p + 1];
        float xs[8] = {a.x, a.y, a.z, a.w, b.x, b.y, b.z, b.w};
        float r[8];
#pragma unroll
        for (int j = 0; j < 8; j++) {                 // j == channel, compile-time
            const float x  = xs[j];
            const float xc = fminf(fmaxf(x, -1.0f), 1.0f);

            int q = (int)fmaf(xc, 512.0f, 512.0f);
            q = min(q, NLUT - 1);
            float2 cell = sL[j][q];                   // {edge[idx+1], idx}
            float dyp = xc - cell.x;
            bool  up  = dyp >= 0.0f;                  // past the next knot?
            int   idx = __float_as_int(cell.y) + (up ? 1 : 0);

            float4 pk = sP[j][idx];                   // {h, delta, d0, t}
            float dy = up ? dyp : dyp + pk.x;         // exact: dy' + h_idx == xc - e0

            // stable quadratic inverse (citardauq), t-packed form
            float dmd  = pk.y - pk.z;                 // delta - d0
            float dyt  = dy * pk.w;                   // dy * t
            float aa   = fmaf(pk.x, dmd, dyt);
            float bb   = fmaf(pk.x, pk.z, -dyt);
            float g    = pk.y * dy;                   // delta*dy = -c
            float disc = fmaxf(fmaf(bb, bb, 4.0f * aa * g), 0.0f);
            float s;  asm("sqrt.approx.f32 %0, %1;" : "=f"(s) : "f"(disc));
            float root = __fdividef(g + g, bb + s);
            float th   = fmaf(-root, root, root);     // root*(1-root)
            float den  = fmaf(pk.w, th, pk.y);
            float pp   = fmaf(fmaf(pk.w, root, dmd + dmd), root, pk.z);
            float num  = (pk.y * pk.y) * pp;
            float lad  = __logf(__fdividef(num, den * den));

            r[j] = (fabsf(x) <= 1.0f) ? (LOG_HALF - lad) : LOG_HALF;
        }
        o4[2 * p]     = make_float4(r[0], r[1], r[2], r[3]);
        o4[2 * p + 1] = make_float4(r[4], r[5], r[6], r[7]);
    }
}

// ---------------------------------------------------------------------------
extern "C" void kernel_launch(void* const* d_in, const int* in_sizes, int n_in,
                              void* d_out, int out_size)
{
    const float* x  = (const float*)d_in[0];
    const float* uw = (const float*)d_in[1];
    const float* uh = (const float*)d_in[2];
    const float* ud = (const float*)d_in[3];

    cudaFuncSetAttribute(spline_fused_kernel,
                         cudaFuncAttributeMaxDynamicSharedMemorySize, SMEM_TOTAL);

    const int npairs = out_size / 8;     // one pair of float4 = one position
    spline_fused_kernel<<<296, 512, SMEM_TOTAL>>>((const float4*)x, (float4*)d_out,
                                                  npairs, uw, uh, ud);
}

// round 8
// speedup vs baseline: 1.2553x; 1.1147x over previous
#include <cuda_runtime.h>
#include <cuda_fp16.h>
#include <cstdint>

// ---------------------------------------------------------------------------
// UniformSpline log-prob (inverse rational-quadratic spline logdet)
//   x: (2097152, 8) f32   uw,uh: (8,128) f32   ud: (8,127) f32
//   out = log(0.5) - logabsdet(x), identity tails -> log(0.5)
//
// Single fused kernel, ONE shared load per element: the direct-index LUT cell
// carries the full bin parameterization {e0, h, delta, half2(d0, t)}. Since
// min bin height (2e-3) > cell width (2/1024), a cell's bin can be exceeded by
// at most one knot, and the next bin's params live in cell q+1.
// ---------------------------------------------------------------------------

#define NCH   8
#define NBINS 128
#define NLUT  1024

// dynamic smem layout (bytes), all 16B-aligned
#define SC_OFF   0                                    // float4 sC[8][NLUT+2]
#define SC_BYTES (NCH * (NLUT + 2) * 16)
#define ST_OFF   (SC_OFF + SC_BYTES)                  // float4 sT[8][128] {h,delta,d0,t}
#define ST_BYTES (NCH * NBINS * 16)
#define SE_OFF   (ST_OFF + ST_BYTES)                  // float sE[8][129]
#define SE_BYTES (NCH * (NBINS + 1) * 4)
#define SMEM_TOTAL (SE_OFF + SE_BYTES)

__device__ __forceinline__ float softplus_md(float v) {
    return 1e-3f + log1pf(expf(v));      // MIN_DERIVATIVE + softplus
}

// Per-warp (one channel) softmax(10u)+min-size cumsum -> knots in [-1,1].
// Lane l owns bins 4l..4l+3; e[0..4] = edges 4l..4l+4.
__device__ __forceinline__ void edges4(const float* __restrict__ src_row,
                                       int l, float e[5]) {
    float u[4], ex[4];
#pragma unroll
    for (int k = 0; k < 4; k++) u[k] = 10.0f * src_row[l * 4 + k];
    float m = fmaxf(fmaxf(u[0], u[1]), fmaxf(u[2], u[3]));
#pragma unroll
    for (int off = 16; off; off >>= 1) m = fmaxf(m, __shfl_xor_sync(0xffffffffu, m, off));
#pragma unroll
    for (int k = 0; k < 4; k++) ex[k] = expf(u[k] - m);
    float ls = ex[0] + ex[1] + ex[2] + ex[3];

    float sc = ls;
#pragma unroll
    for (int off = 1; off < 32; off <<= 1) {
        float v = __shfl_up_sync(0xffffffffu, sc, off);
        if (l >= off) sc += v;
    }
    const float invS = 1.0f / __shfl_sync(0xffffffffu, sc, 31);
    float ce = sc - ls;

    e[0] = (l == 0) ? -1.0f
                    : 2.0f * (1e-3f * (float)(4 * l) + 0.872f * ce * invS) - 1.0f;
#pragma unroll
    for (int k = 0; k < 4; k++) {
        ce += ex[k];
        int j = l * 4 + k + 1;
        e[k + 1] = (j == NBINS) ? 1.0f
                                : 2.0f * (1e-3f * (float)j + 0.872f * ce * invS) - 1.0f;
    }
}

__global__ void __launch_bounds__(1024, 1)
spline_fused_kernel(const float4* __restrict__ x4, float4* __restrict__ o4, int npairs,
                    const float* __restrict__ uw, const float* __restrict__ uh,
                    const float* __restrict__ ud)
{
    extern __shared__ unsigned char smem_raw[];
    float4 (*sC)[NLUT + 2] = (float4 (*)[NLUT + 2])(smem_raw + SC_OFF); // {e0,h,delta,h2(d0,t)}
    float4 (*sT)[NBINS]    = (float4 (*)[NBINS])   (smem_raw + ST_OFF); // {h,delta,d0,t}
    float  (*sE)[NBINS + 1]= (float (*)[NBINS + 1])(smem_raw + SE_OFF); // cumheight knots

    const int tid = threadIdx.x;
    const int l   = tid & 31;

    // ---- per-channel table build: warps 0..7 -> channel = warp id ----
    if (tid < 256) {
        const int c0 = tid >> 5;
        const float DI = logf(expf(1.0f - 1e-3f) - 1.0f);
        const float DT = softplus_md(DI);            // tail derivative == 1.0

        float ew[5], eh[5];
        edges4(uw + c0 * NBINS, l, ew);
        edges4(uh + c0 * NBINS, l, eh);

        float dd[5];
#pragma unroll
        for (int m2 = 0; m2 < 5; m2++) {
            int k = 4 * l + m2;
            dd[m2] = (k == 0 || k == NBINS) ? DT
                     : softplus_md(ud[c0 * (NBINS - 1) + k - 1]);
        }

#pragma unroll
        for (int k = 0; k < 4; k++) sE[c0][4 * l + k] = eh[k];
        if (l == 31) sE[c0][NBINS] = eh[4];

#pragma unroll
        for (int k = 0; k < 4; k++) {
            float h  = eh[k + 1] - eh[k];
            float dl = h / (ew[k + 1] - ew[k]);
            sT[c0][4 * l + k] = make_float4(h, dl, dd[k], dd[k] + dd[k + 1] - 2.0f * dl);
        }
    }
    __syncthreads();

    // ---- LUT: 128 threads per channel, 8 cells each ----
    {
        const int c     = tid >> 7;
        const int cell0 = (tid & 127) * 8;
        const float* E  = &sE[c][0];
        float v = (float)cell0 * (1.0f / 512.0f) - 1.0f;
        int lo = 0;                                   // largest k<=127 with E[k] <= cell_lo
#pragma unroll
        for (int step = 64; step; step >>= 1)
            if (lo + step <= NBINS - 1 && E[lo + step] <= v) lo += step;
        for (int q = 0; q < 8; q++) {
            float vq = (float)(cell0 + q) * (1.0f / 512.0f) - 1.0f;
            while (lo < NBINS - 1 && E[lo + 1] <= vq) lo++;
            float4 tq = sT[c][lo];
            __half2 hp = __floats2half2_rn(tq.z, tq.w);
            unsigned hu = *reinterpret_cast<unsigned*>(&hp);
            sC[c][cell0 + q] = make_float4(E[lo], tq.x, tq.y, __uint_as_float(hu));
        }
        if ((tid & 127) == 127) sC[c][NLUT] = sC[c][NLUT - 1];  // sentinel
    }
    __syncthreads();

    // ---- main pass: one position (8 channels) per iteration ----
    const float LOG_HALF = -0.6931471805599453f;
    const int stride = gridDim.x * blockDim.x;

    for (int p = blockIdx.x * blockDim.x + tid; p < npairs; p += stride) {
        float4 a = x4[2 * p];
        float4 b = x4[2 * p + 1];
        float xs[8] = {a.x, a.y, a.z, a.w, b.x, b.y, b.z, b.w};
        float r[8];
#pragma unroll
        for (int j = 0; j < 8; j++) {                 // j == channel, compile-time
            const float x  = xs[j];
            const float xc = fminf(fmaxf(x, -1.0f), 1.0f);

            int q = (int)fmaf(xc, 512.0f, 512.0f);
            q = min(q, NLUT - 1);
            float4 cl = sC[j][q];                     // {e0, h, delta, half2(d0,t)}
            float dy = xc - cl.x;
            if (dy > cl.y) {                          // crossed the one knot in this cell
                cl = sC[j][q + 1];
                dy = xc - cl.x;
            }
            unsigned hu = __float_as_uint(cl.w);
            float2 dt = __half22float2(*reinterpret_cast<__half2*>(&hu));
            const float h = cl.y, dl = cl.z, d0 = dt.x, t = dt.y;

            // stable quadratic inverse (citardauq), t-packed form
            float dmd  = dl - d0;
            float dyt  = dy * t;
            float aa   = fmaf(h, dmd, dyt);
            float bb   = fmaf(h, d0, -dyt);
            float g    = dl * dy;                     // -c
            float disc = fmaxf(fmaf(bb, bb, 4.0f * aa * g), 0.0f);
            float s;  asm("sqrt.approx.f32 %0, %1;" : "=f"(s) : "f"(disc));
            float root = __fdividef(g + g, bb + s);
            float th   = fmaf(-root, root, root);     // root*(1-root)
            float den  = fmaf(t, th, dl);
            float pp   = fmaf(fmaf(t, root, dmd + dmd), root, d0);
            float num  = (dl * dl) * pp;
            float lad  = __logf(__fdividef(num, den * den));

            r[j] = (fabsf(x) <= 1.0f) ? (LOG_HALF - lad) : LOG_HALF;
        }
        o4[2 * p]     = make_float4(r[0], r[1], r[2], r[3]);
        o4[2 * p + 1] = make_float4(r[4], r[5], r[6], r[7]);
    }
}

// ---------------------------------------------------------------------------
extern "C" void kernel_launch(void* const* d_in, const int* in_sizes, int n_in,
                              void* d_out, int out_size)
{
    const float* x  = (const float*)d_in[0];
    const float* uw = (const float*)d_in[1];
    const float* uh = (const float*)d_in[2];
    const float* ud = (const float*)d_in[3];

    cudaFuncSetAttribute(spline_fused_kernel,
                         cudaFuncAttributeMaxDynamicSharedMemorySize, SMEM_TOTAL);

    const int npairs = out_size / 8;     // one pair of float4 = one position
    spline_fused_kernel<<<148, 1024, SMEM_TOTAL>>>((const float4*)x, (float4*)d_out,
                                                   npairs, uw, uh, ud);
}

// round 9
// speedup vs baseline: 1.2560x; 1.0006x over previous
#include <cuda_runtime.h>
#include <cuda_fp16.h>
#include <cstdint>

// ---------------------------------------------------------------------------
// UniformSpline log-prob (inverse rational-quadratic spline logdet)
//   x: (2097152, 8) f32   uw,uh: (8,128) f32   ud: (8,127) f32
//   out = log(0.5) - logabsdet(x), identity tails -> log(0.5)
//
// Fused kernel; direct-index LUT cell = {e0, h, delta, half2(d0,t)} -> ONE
// LDS.128 per element. Polynomial chain evaluated two channels at a time with
// packed f32x2 FMA (Blackwell-only; ptxas never auto-emits these).
// ---------------------------------------------------------------------------

#define NCH   8
#define NBINS 128
#define NLUT  1024

#define SC_OFF   0                                    // float4 sC[8][NLUT+2]
#define SC_BYTES (NCH * (NLUT + 2) * 16)
#define ST_OFF   (SC_OFF + SC_BYTES)                  // float4 sT[8][128]
#define ST_BYTES (NCH * NBINS * 16)
#define SE_OFF   (ST_OFF + ST_BYTES)                  // float sE[8][129]
#define SE_BYTES (NCH * (NBINS + 1) * 4)
#define SMEM_TOTAL (SE_OFF + SE_BYTES)

typedef unsigned long long u64;
#define PK(o,a,b)     asm("mov.b64 %0, {%1, %2};"      : "=l"(o) : "f"(a), "f"(b))
#define UPK(a,b,i)    asm("mov.b64 {%0, %1}, %2;"      : "=f"(a), "=f"(b) : "l"(i))
#define MUL2(o,a,b)   asm("mul.rn.f32x2 %0, %1, %2;"   : "=l"(o) : "l"(a), "l"(b))
#define ADD2(o,a,b)   asm("add.rn.f32x2 %0, %1, %2;"   : "=l"(o) : "l"(a), "l"(b))
#define SUB2(o,a,b)   asm("sub.rn.f32x2 %0, %1, %2;"   : "=l"(o) : "l"(a), "l"(b))
#define FMA2(o,a,b,c) asm("fma.rn.f32x2 %0, %1, %2, %3;" : "=l"(o) : "l"(a), "l"(b), "l"(c))
#define RCPA(o,a)     asm("rcp.approx.f32 %0, %1;"     : "=f"(o) : "f"(a))
#define SQRTA(o,a)    asm("sqrt.approx.f32 %0, %1;"    : "=f"(o) : "f"(a))

__device__ __forceinline__ float softplus_md(float v) {
    return 1e-3f + log1pf(expf(v));      // MIN_DERIVATIVE + softplus
}

// Per-warp (one channel) softmax(10u)+min-size cumsum -> knots in [-1,1].
__device__ __forceinline__ void edges4(const float* __restrict__ src_row,
                                       int l, float e[5]) {
    float u[4], ex[4];
#pragma unroll
    for (int k = 0; k < 4; k++) u[k] = 10.0f * src_row[l * 4 + k];
    float m = fmaxf(fmaxf(u[0], u[1]), fmaxf(u[2], u[3]));
#pragma unroll
    for (int off = 16; off; off >>= 1) m = fmaxf(m, __shfl_xor_sync(0xffffffffu, m, off));
#pragma unroll
    for (int k = 0; k < 4; k++) ex[k] = expf(u[k] - m);
    float ls = ex[0] + ex[1] + ex[2] + ex[3];

    float sc = ls;
#pragma unroll
    for (int off = 1; off < 32; off <<= 1) {
        float v = __shfl_up_sync(0xffffffffu, sc, off);
        if (l >= off) sc += v;
    }
    const float invS = 1.0f / __shfl_sync(0xffffffffu, sc, 31);
    float ce = sc - ls;

    e[0] = (l == 0) ? -1.0f
                    : 2.0f * (1e-3f * (float)(4 * l) + 0.872f * ce * invS) - 1.0f;
#pragma unroll
    for (int k = 0; k < 4; k++) {
        ce += ex[k];
        int j = l * 4 + k + 1;
        e[k + 1] = (j == NBINS) ? 1.0f
                                : 2.0f * (1e-3f * (float)j + 0.872f * ce * invS) - 1.0f;
    }
}

__global__ void __launch_bounds__(1024, 1)
spline_fused_kernel(const float4* __restrict__ x4, float4* __restrict__ o4, int npairs,
                    const float* __restrict__ uw, const float* __restrict__ uh,
                    const float* __restrict__ ud)
{
    extern __shared__ unsigned char smem_raw[];
    float4 (*sC)[NLUT + 2] = (float4 (*)[NLUT + 2])(smem_raw + SC_OFF);
    float4 (*sT)[NBINS]    = (float4 (*)[NBINS])   (smem_raw + ST_OFF);
    float  (*sE)[NBINS + 1]= (float (*)[NBINS + 1])(smem_raw + SE_OFF);

    const int tid = threadIdx.x;
    const int l   = tid & 31;

    // ---- per-channel table build: warps 0..7 -> channel = warp id ----
    if (tid < 256) {
        const int c0 = tid >> 5;
        const float DI = logf(expf(1.0f - 1e-3f) - 1.0f);
        const float DT = softplus_md(DI);            // tail derivative == 1.0

        float ew[5], eh[5];
        edges4(uw + c0 * NBINS, l, ew);
        edges4(uh + c0 * NBINS, l, eh);

        float dd[5];
#pragma unroll
        for (int m2 = 0; m2 < 5; m2++) {
            int k = 4 * l + m2;
            dd[m2] = (k == 0 || k == NBINS) ? DT
                     : softplus_md(ud[c0 * (NBINS - 1) + k - 1]);
        }

#pragma unroll
        for (int k = 0; k < 4; k++) sE[c0][4 * l + k] = eh[k];
        if (l == 31) sE[c0][NBINS] = eh[4];

#pragma unroll
        for (int k = 0; k < 4; k++) {
            float h  = eh[k + 1] - eh[k];
            float dl = h / (ew[k + 1] - ew[k]);
            sT[c0][4 * l + k] = make_float4(h, dl, dd[k], dd[k] + dd[k + 1] - 2.0f * dl);
        }
    }
    __syncthreads();

    // ---- LUT: 128 threads per channel, 8 cells each ----
    {
        const int c     = tid >> 7;
        const int cell0 = (tid & 127) * 8;
        const float* E  = &sE[c][0];
        float v = (float)cell0 * (1.0f / 512.0f) - 1.0f;
        int lo = 0;
#pragma unroll
        for (int step = 64; step; step >>= 1)
            if (lo + step <= NBINS - 1 && E[lo + step] <= v) lo += step;
        for (int q = 0; q < 8; q++) {
            float vq = (float)(cell0 + q) * (1.0f / 512.0f) - 1.0f;
            while (lo < NBINS - 1 && E[lo + 1] <= vq) lo++;
            float4 tq = sT[c][lo];
            __half2 hp = __floats2half2_rn(tq.z, tq.w);
            unsigned hu = *reinterpret_cast<unsigned*>(&hp);
            sC[c][cell0 + q] = make_float4(E[lo], tq.x, tq.y, __uint_as_float(hu));
        }
        if ((tid & 127) == 127) sC[c][NLUT] = sC[c][NLUT - 1];  // sentinel
    }
    __syncthreads();

    // ---- main pass: one position (8 channels) per iteration ----
    const float LOG_HALF = -0.6931471805599453f;
    const int stride = gridDim.x * blockDim.x;

    u64 ONE2, FOUR2;
    PK(ONE2, 1.0f, 1.0f);
    PK(FOUR2, 4.0f, 4.0f);

    for (int p = blockIdx.x * blockDim.x + tid; p < npairs; p += stride) {
        float4 av = x4[2 * p];
        float4 bv = x4[2 * p + 1];
        float xs[8] = {av.x, av.y, av.z, av.w, bv.x, bv.y, bv.z, bv.w};
        float r[8];
#pragma unroll
        for (int j = 0; j < 8; j += 2) {              // pair of channels, compile-time
            const float xa = xs[j],   xb = xs[j + 1];
            const float xca = fminf(fmaxf(xa, -1.0f), 1.0f);
            const float xcb = fminf(fmaxf(xb, -1.0f), 1.0f);

            int qa = min((int)fmaf(xca, 512.0f, 512.0f), NLUT - 1);
            int qb = min((int)fmaf(xcb, 512.0f, 512.0f), NLUT - 1);
            float4 ca = sC[j][qa];
            float4 cb = sC[j + 1][qb];
            float dya = xca - ca.x;
            if (dya > ca.y) { ca = sC[j][qa + 1];     dya = xca - ca.x; }
            float dyb = xcb - cb.x;
            if (dyb > cb.y) { cb = sC[j + 1][qb + 1]; dyb = xcb - cb.x; }

            unsigned hua = __float_as_uint(ca.w);
            unsigned hub = __float_as_uint(cb.w);
            float2 dta = __half22float2(*reinterpret_cast<__half2*>(&hua));
            float2 dtb = __half22float2(*reinterpret_cast<__half2*>(&hub));

            // pack two channels into f32x2 lanes
            u64 DY, H, DL, D0, T;
            PK(DY, dya, dyb);
            PK(H,  ca.y, cb.y);
            PK(DL, ca.z, cb.z);
            PK(D0, dta.x, dtb.x);
            PK(T,  dta.y, dtb.y);

            u64 DYT, DMD, AA, HD0, BB, G, AG, AG4, DISC;
            MUL2(DYT, DY, T);
            SUB2(DMD, DL, D0);
            FMA2(AA, H, DMD, DYT);
            MUL2(HD0, H, D0);
            SUB2(BB, HD0, DYT);
            MUL2(G, DL, DY);
            MUL2(AG, AA, G);
            MUL2(AG4, AG, FOUR2);
            FMA2(DISC, BB, BB, AG4);

            // scalar MUFU segment: sqrt + rcp per lane
            float da, db, bba, bbb;
            UPK(da, db, DISC);
            UPK(bba, bbb, BB);
            da = fmaxf(da, 0.0f);  db = fmaxf(db, 0.0f);
            float sa, sb;  SQRTA(sa, da);  SQRTA(sb, db);
            float rwa, rwb;
            RCPA(rwa, bba + sa);
            RCPA(rwb, bbb + sb);

            u64 RW, G2, ROOT, OMR, TH, DEN, DMD2, PPI, PP, DL2, NUM, DEN2;
            PK(RW, rwa, rwb);
            ADD2(G2, G, G);
            MUL2(ROOT, G2, RW);
            SUB2(OMR, ONE2, ROOT);
            MUL2(TH, ROOT, OMR);
            FMA2(DEN, T, TH, DL);
            ADD2(DMD2, DMD, DMD);
            FMA2(PPI, T, ROOT, DMD2);
            FMA2(PP, PPI, ROOT, D0);
            MUL2(DL2, DL, DL);
            MUL2(NUM, DL2, PP);
            MUL2(DEN2, DEN, DEN);

            float na, nb, dena, denb;
            UPK(na, nb, NUM);
            UPK(dena, denb, DEN2);
            float lada = __logf(__fdividef(na, dena));
            float ladb = __logf(__fdividef(nb, denb));

            r[j]     = (xa == xca) ? (LOG_HALF - lada) : LOG_HALF;
            r[j + 1] = (xb == xcb) ? (LOG_HALF - ladb) : LOG_HALF;
        }
        o4[2 * p]     = make_float4(r[0], r[1], r[2], r[3]);
        o4[2 * p + 1] = make_float4(r[4], r[5], r[6], r[7]);
    }
}

// ---------------------------------------------------------------------------
extern "C" void kernel_launch(void* const* d_in, const int* in_sizes, int n_in,
                              void* d_out, int out_size)
{
    const float* x  = (const float*)d_in[0];
    const float* uw = (const float*)d_in[1];
    const float* uh = (const float*)d_in[2];
    const float* ud = (const float*)d_in[3];

    cudaFuncSetAttribute(spline_fused_kernel,
                         cudaFuncAttributeMaxDynamicSharedMemorySize, SMEM_TOTAL);

    const int npairs = out_size / 8;     // one pair of float4 = one position
    spline_fused_kernel<<<148, 1024, SMEM_TOTAL>>>((const float4*)x, (float4*)d_out,
                                                   npairs, uw, uh, ud);
}